// round 13
// baseline (speedup 1.0000x reference)
#include <cuda_runtime.h>
typedef unsigned long long u64;

#define Bn 16
#define Cn 32
#define Sn 256
#define Mn 12
#define Rn 24
#define Ln 4
#define BCn (Bn*Cn)
#define WTN (Ln*Rn*Mn*Cn*Cn)
#define SS (Sn*Sn)

__device__ float g_h[(size_t)BCn*SS];
__device__ float g_Y[(size_t)Bn*Sn*Rn*Cn];    // [b][y][q][c], q<12 re, q>=12 im
__device__ u64   g_T2[(size_t)Bn*Sn*Cn*Mn];   // [b][y][o][k] {tr,ti}
__device__ float g_Wtr[WTN];
__device__ float g_Wti[WTN];
__device__ float g_trigF[Rn*128];             // folded: rows 0-11 cos(k w), 12-23 sin(k w), w<128
__device__ u64   g_tcF[Rn*Sn];                // {c,c} at ky(r)*h
__device__ u64   g_tsF[Rn*Sn];

__device__ __forceinline__ u64 pk2(float x, float y) {
    u64 r; asm("mov.b64 %0,{%1,%2};" : "=l"(r) : "f"(x), "f"(y)); return r;
}
__device__ __forceinline__ void up2(u64 a, float& x, float& y) {
    asm("mov.b64 {%0,%1},%2;" : "=f"(x), "=f"(y) : "l"(a));
}
__device__ __forceinline__ u64 f2fma(u64 a, u64 b, u64 c) {
    u64 d; asm("fma.rn.f32x2 %0,%1,%2,%3;" : "=l"(d) : "l"(a), "l"(b), "l"(c)); return d;
}

__global__ void k_setupA() {   // launch 0
    int q = blockIdx.x, w = threadIdx.x;
    if (w >= 128) return;
    int kq = (q < Mn) ? q : q - Mn;
    float s, c;
    sincospif((float)((kq*w) & 255) * (2.0f/256.0f), &s, &c);
    g_trigF[q*128 + w] = (q < Mn) ? c : s;
}
__global__ void k_setupB() {   // launch 1
    int q = blockIdx.x, w = threadIdx.x;
    int ky = (q < Mn) ? q : 232 + q;
    float s, c;
    sincospif((float)((ky*w) & 255) * (2.0f/256.0f), &s, &c);
    g_tcF[q*Sn + w] = pk2(c, c);
    g_tsF[q*Sn + w] = pk2(s, s);
}

__global__ void k_wt(const float* __restrict__ w1r, const float* __restrict__ w1i,
                     const float* __restrict__ w2r, const float* __restrict__ w2i) {
    int flat = blockIdx.x*256 + threadIdx.x;   // launch 2
    if (flat >= WTN) return;
    int o = flat & 31;
    int i = (flat >> 5) & 31;
    int k = (flat >> 10) % Mn;
    int r = (flat / (Mn*Cn*Cn)) % Rn;
    int l =  flat / (Rn*Mn*Cn*Cn);
    int ky = (r < Mn) ? r : r - Mn;
    size_t s = ((((size_t)l*Cn + i)*Cn + o)*Mn + ky)*Mn + k;
    const float sc = 1.0f/65536.0f;
    if (r < Mn) { g_Wtr[flat] = w1r[s]*sc; g_Wti[flat] = w1i[s]*sc; }
    else        { g_Wtr[flat] = w2r[s]*sc; g_Wti[flat] = w2i[s]*sc; }
}

// ---- k_modes: byte-identical to the 1084us version ----
__global__ void __launch_bounds__(768) k_modes(int l) {
    extern __shared__ u64 smu[];
    u64* sY = smu;              // [256][33] {re,im}
    u64* sZ = smu + 256*33;     // [c][25]
    u64* sO = sZ + 32*25;       // [o][25] padded to 33 rows
    int b = blockIdx.x / Mn, k = blockIdx.x % Mn;
    int t = threadIdx.x;
    const float* yb = g_Y + (size_t)b*Sn*Rn*Cn;
    for (int idx = t; idx < Cn*Sn; idx += 768) {
        int y = idx >> 5, c = idx & 31;
        const float* yp = yb + (size_t)y*(Rn*Cn) + k*Cn + c;
        sY[y*33 + c] = pk2(yp[0], yp[Mn*Cn]);
    }
    __syncthreads();
    int r = t >> 5, lane = t & 31;
    {
        u64 pm = (r & 1) ? pk2(-1.f, -1.f) : pk2(1.f, 1.f);
        const u64* tc = g_tcF + r*Sn;
        const u64* ts = g_tsF + r*Sn;
        u64 accP = 0, accQ = 0;
        #pragma unroll 4
        for (int hp = 0; hp < 128; hp++) {
            u64 ya = sY[hp*33 + lane];
            u64 yc = sY[(hp+128)*33 + lane];
            u64 u = f2fma(yc, pm, ya);
            accP = f2fma(u, __ldg(tc + hp), accP);
            accQ = f2fma(u, __ldg(ts + hp), accQ);
        }
        float px, py, qx, qy; up2(accP, px, py); up2(accQ, qx, qy);
        sZ[lane*25 + r] = pk2(px + qy, py - qx);
    }
    __syncthreads();
    {
        size_t wb = ((size_t)((l*Rn + r)*Mn + k))*(Cn*Cn) + lane;
        float orr = 0.f, oii = 0.f;
        #pragma unroll 8
        for (int i = 0; i < Cn; i++) {
            float zr, zi; up2(sZ[i*25 + r], zr, zi);
            float ar = __ldg(g_Wtr + wb + (size_t)i*Cn);
            float ai = __ldg(g_Wti + wb + (size_t)i*Cn);
            orr += zr*ar - zi*ai;
            oii += zr*ai + zi*ar;
        }
        sO[lane*25 + r] = pk2(orr, oii);
    }
    __syncthreads();
    {
        int h = t & 255, third = t >> 8;
        int o0 = third*11;
        int on = (third == 2) ? 10 : 11;
        u64 accP[11], accQ[11];
        #pragma unroll
        for (int i = 0; i < 11; i++) { accP[i] = 0; accQ[i] = 0; }
        for (int rr = 0; rr < Rn; rr++) {
            u64 c2 = __ldg(g_tcF + rr*Sn + h);
            u64 s2 = __ldg(g_tsF + rr*Sn + h);
            #pragma unroll
            for (int i = 0; i < 11; i++) {
                u64 O = sO[(o0 + i)*25 + rr];
                accP[i] = f2fma(O, c2, accP[i]);
                accQ[i] = f2fma(O, s2, accQ[i]);
            }
        }
        u64* Tb = g_T2 + ((size_t)(b*Sn + h)*Cn)*Mn + k;
        #pragma unroll
        for (int i = 0; i < 11; i++) if (i < on) {
            float px, py, qx, qy; up2(accP[i], px, py); up2(accQ[i], qx, qy);
            Tb[(size_t)(o0 + i)*Mn] = pk2(px - qy, qx + py);
        }
    }
}

// ---- k_layer: 1084us conv; e/d-prefolded, parity-split, f32x2 DFT ----
template<int MODE>
__global__ void __launch_bounds__(256) k_layer(
    const float* __restrict__ x,
    const float* __restrict__ pw, const float* __restrict__ pb,
    const float* __restrict__ wsw, const float* __restrict__ wsb,
    const float* __restrict__ qw, const float* __restrict__ qb,
    int l, float* __restrict__ out)
{
    extern __shared__ u64 smu[];
    u64* s_wsu  = smu;                       // [32][16] {w[o][2i], w[o][2i+1]}
    u64* s_t12u = smu + 512;                 // [32][12] {tr,ti}
    float* s_x    = (float*)(smu + 896);     // [32][264]: v -> e(0..127), d(132..259)
    float* s_trig = s_x + Cn*264;            // [24][132] folded
    float* s_wb   = s_trig + Rn*132;         // [32]
    float* s_qw   = s_wb + Cn;               // [32]

    int t = threadIdx.x;
    int b = blockIdx.x >> 8, y = blockIdx.x & 255;
    int w = t;
    float* hrow = g_h + (((size_t)b*Cn)*Sn + y)*Sn + w;

    // hoist gmem latency above staging; pack channel pairs
    u64 hin2[16];
    if (MODE >= 1) {
        #pragma unroll
        for (int i = 0; i < 16; i++)
            hin2[i] = pk2(hrow[(size_t)(2*i)*SS], hrow[(size_t)(2*i+1)*SS]);
    }

    for (int i = t; i < Rn*128; i += 256)
        s_trig[(i >> 7)*132 + (i & 127)] = g_trigF[i];
    if (MODE >= 1) {
        const u64* T2 = g_T2 + (size_t)blockIdx.x * (Cn*Mn);
        for (int i = t; i < Cn*Mn; i += 256) s_t12u[i] = T2[i];     // coalesced
        const float2* wsrc = (const float2*)(wsw + l*Cn*Cn);
        for (int i = t; i < Cn*16; i += 256) {
            float2 wv = wsrc[i];
            s_wsu[i] = pk2(wv.x, wv.y);
        }
        if (t < Cn) { s_wb[t] = wsb[l*Cn + t]; s_qw[t] = qw[t]; }
    }
    __syncthreads();

    if (MODE == 0) {
        float xin = x[(size_t)blockIdx.x*Sn + w];
        float gy = -1.f + (2.f/255.f)*(float)y;
        float gx = -1.f + (2.f/255.f)*(float)w;
        #pragma unroll 8
        for (int c = 0; c < Cn; c++) {
            float v = pw[c*3+0]*xin + pw[c*3+1]*gy + pw[c*3+2]*gx + pb[c];
            hrow[(size_t)c*SS] = v;
            s_x[c*264 + w] = v;
        }
    } else {
        // trig2[k] = {sg*2*cos(kw), -sg*2*sin(kw)}; trig2[0] = {1,0} (DC, imag ignored)
        u64 trig2[Mn];
        {
            int wl = w & 127;
            trig2[0] = pk2(1.f, 0.f);
            #pragma unroll
            for (int k = 1; k < Mn; k++) {
                float c = s_trig[k*132 + wl];
                float s = s_trig[(Mn + k)*132 + wl];
                float sg = ((w >> 7) & (k & 1)) ? -2.f : 2.f;
                trig2[k] = pk2(sg*c, -sg*s);
            }
        }
        float proj = 0.f;
        #pragma unroll 2
        for (int o = 0; o < Cn; o++) {
            const ulonglong2* wp = (const ulonglong2*)(s_wsu + o*16);   // broadcast
            u64 acc0 = pk2(s_wb[o], 0.f), acc1 = 0;
            #pragma unroll
            for (int j = 0; j < 8; j++) {
                ulonglong2 q2 = wp[j];
                acc0 = f2fma(hin2[2*j],   q2.x, acc0);
                acc1 = f2fma(hin2[2*j+1], q2.y, acc1);
            }
            const ulonglong2* tp = (const ulonglong2*)(s_t12u + o*12);  // broadcast
            u64 fac0 = 0, fac1 = 0;
            #pragma unroll
            for (int j = 0; j < 6; j++) {
                ulonglong2 tq = tp[j];
                fac0 = f2fma(tq.x, trig2[2*j],   fac0);
                fac1 = f2fma(tq.y, trig2[2*j+1], fac1);
            }
            float a0x, a0y, a1x, a1y, f0x, f0y, f1x, f1y;
            up2(acc0, a0x, a0y); up2(acc1, a1x, a1y);
            up2(fac0, f0x, f0y); up2(fac1, f1x, f1y);
            float v = (a0x + a0y) + (a1x + a1y) + (f0x + f0y) + (f1x + f1y);
            if (MODE == 1) {
                v = fmaxf(v, 0.f);
                hrow[(size_t)o*SS] = v;
                s_x[o*264 + w] = v;
            } else {
                proj += s_qw[o]*v;
            }
        }
        if (MODE == 2) {
            out[(size_t)blockIdx.x*Sn + w] = proj + qb[0];
            return;
        }
    }
    __syncthreads();

    // in-place e/d fold: e -> cols 0..127, d -> cols 132..259 (reg-buffered)
    {
        float eb[16], db[16];
        #pragma unroll
        for (int it = 0; it < 16; it++) {
            int idx = t + it*256;
            int c = idx >> 7, wp2 = idx & 127;
            float lo = s_x[c*264 + wp2];
            float hi = s_x[c*264 + wp2 + 128];
            eb[it] = lo + hi;
            db[it] = lo - hi;
        }
        __syncthreads();
        #pragma unroll
        for (int it = 0; it < 16; it++) {
            int idx = t + it*256;
            int c = idx >> 7, wp2 = idx & 127;
            s_x[c*264 + wp2]       = eb[it];
            s_x[c*264 + 132 + wp2] = db[it];
        }
    }
    __syncthreads();

    // parity-split f32x2 row-DFT: thread = (o = t>>3, par = (t>>2)&1, g3 = t&3)
    // rows q0, q0+2, q0+4 with q0 = 6*g3 + par; data = e (par 0) or d (par 1)
    {
        int o = t >> 3, par = (t >> 2) & 1, g3 = t & 3;
        int q0 = 6*g3 + par;
        const ulonglong2* dat = (const ulonglong2*)(s_x + o*264 + par*132);
        const ulonglong2* t0p = (const ulonglong2*)(s_trig + q0*132);
        const ulonglong2* t1p = (const ulonglong2*)(s_trig + (q0+2)*132);
        const ulonglong2* t2p = (const ulonglong2*)(s_trig + (q0+4)*132);
        u64 a0 = 0, a1 = 0, a2 = 0;
        #pragma unroll 8
        for (int j = 0; j < 32; j++) {
            ulonglong2 d2 = dat[j];
            ulonglong2 u0 = t0p[j], u1 = t1p[j], u2 = t2p[j];
            a0 = f2fma(d2.x, u0.x, a0); a0 = f2fma(d2.y, u0.y, a0);
            a1 = f2fma(d2.x, u1.x, a1); a1 = f2fma(d2.y, u1.y, a1);
            a2 = f2fma(d2.x, u2.x, a2); a2 = f2fma(d2.y, u2.y, a2);
        }
        float x0, y0, x1, y1, x2, y2;
        up2(a0, x0, y0); up2(a1, x1, y1); up2(a2, x2, y2);
        float r0 = x0 + y0, r1 = x1 + y1, r2 = x2 + y2;
        float* yb = g_Y + (size_t)blockIdx.x*(Rn*Cn);
        yb[(q0  )*Cn + o] = (q0   >= Mn) ? -r0 : r0;   // Yi = -sum v*sin
        yb[(q0+2)*Cn + o] = (q0+2 >= Mn) ? -r1 : r1;
        yb[(q0+4)*Cn + o] = (q0+4 >= Mn) ? -r2 : r2;
    }
}

#define SMEM_LAYER (896*8 + (Cn*264 + Rn*132 + 2*Cn)*4)
#define SMEM_MODES ((256*33 + 32*25 + 33*25)*8)

extern "C" void kernel_launch(void* const* d_in, const int* in_sizes, int n_in,
                              void* d_out, int out_size) {
    (void)in_sizes; (void)n_in; (void)out_size;
    const float* x    = (const float*)d_in[0];
    const float* p_w  = (const float*)d_in[1];
    const float* p_b  = (const float*)d_in[2];
    const float* ws_w = (const float*)d_in[3];
    const float* ws_b = (const float*)d_in[4];
    const float* w1r  = (const float*)d_in[5];
    const float* w1i  = (const float*)d_in[6];
    const float* w2r  = (const float*)d_in[7];
    const float* w2i  = (const float*)d_in[8];
    const float* q_w  = (const float*)d_in[9];
    const float* q_b  = (const float*)d_in[10];
    float* out = (float*)d_out;

    cudaFuncSetAttribute(k_layer<0>, cudaFuncAttributeMaxDynamicSharedMemorySize, SMEM_LAYER);
    cudaFuncSetAttribute(k_layer<1>, cudaFuncAttributeMaxDynamicSharedMemorySize, SMEM_LAYER);
    cudaFuncSetAttribute(k_layer<2>, cudaFuncAttributeMaxDynamicSharedMemorySize, SMEM_LAYER);
    cudaFuncSetAttribute(k_modes,    cudaFuncAttributeMaxDynamicSharedMemorySize, SMEM_MODES);

    k_setupA<<<Rn, Sn>>>();
    k_setupB<<<Rn, Sn>>>();
    k_wt<<<(WTN + 255)/256, 256>>>(w1r, w1i, w2r, w2i);
    k_layer<0><<<Bn*Sn, 256, SMEM_LAYER>>>(x, p_w, p_b, nullptr, nullptr, nullptr, nullptr, 0, out);
    for (int l = 0; l < Ln; l++) {
        k_modes<<<Bn*Mn, 768, SMEM_MODES>>>(l);
        if (l < Ln - 1)
            k_layer<1><<<Bn*Sn, 256, SMEM_LAYER>>>(nullptr, nullptr, nullptr,
                                                   ws_w, ws_b, q_w, q_b, l, out);
        else
            k_layer<2><<<Bn*Sn, 256, SMEM_LAYER>>>(nullptr, nullptr, nullptr,
                                                   ws_w, ws_b, q_w, q_b, l, out);
    }
}